// round 1
// baseline (speedup 1.0000x reference)
#include <cuda_runtime.h>
#include <math.h>

// Problem shape (fixed by setup_inputs)
#define Bn 2048
#define Kn 256
#define Dn 512

#define BM 16      // rows per CTA  -> 128 CTAs
#define DC 32      // d-chunk staged in smem for phase B
#define KC 16      // k-chunk staged in smem for phase C
#define XPITCH 18  // padded pitch for transposed X tiles (bank-conflict relief)

// __device__ scratch (allocation-free per harness rules)
__device__ float g_bwt [Dn * Kn];   // bw transposed: [d][k]
__device__ float g_cw2t[Dn * Kn];   // -2*bw*c transposed: [d][k]
__device__ float g_w   [Kn * Dn];   // softplus(raw_weights): [k][d]
__device__ float g_ck  [Kn];        // sum_d bw*c^2

// ---------------------------------------------------------------------------
// Prep 1: transpose + precompute elementwise terms
// ---------------------------------------------------------------------------
__global__ void prep_kernel(const float* __restrict__ centers,
                            const float* __restrict__ bandwidths,
                            const float* __restrict__ raw_weights) {
    int i = blockIdx.x * blockDim.x + threadIdx.x;
    if (i >= Kn * Dn) return;
    int k = i >> 9;          // /Dn
    int d = i & (Dn - 1);
    float b = bandwidths[i];
    float c = centers[i];
    float r = raw_weights[i];
    g_bwt [d * Kn + k] = b;
    g_cw2t[d * Kn + k] = -2.0f * b * c;
    // numerically stable softplus: max(x,0) + log1p(exp(-|x|))
    g_w[i] = fmaxf(r, 0.0f) + log1pf(expf(-fabsf(r)));
}

// ---------------------------------------------------------------------------
// Prep 2: ck[k] = sum_d bw[k,d] * c[k,d]^2   (one block per k)
// ---------------------------------------------------------------------------
__global__ void prep_ck_kernel(const float* __restrict__ centers,
                               const float* __restrict__ bandwidths) {
    int k = blockIdx.x;
    float s = 0.0f;
    for (int d = threadIdx.x; d < Dn; d += blockDim.x) {
        float c = centers[k * Dn + d];
        s = fmaf(bandwidths[k * Dn + d] * c, c, s);
    }
    __shared__ float red[4];
    #pragma unroll
    for (int o = 16; o > 0; o >>= 1)
        s += __shfl_down_sync(0xffffffffu, s, o);
    if ((threadIdx.x & 31) == 0) red[threadIdx.x >> 5] = s;
    __syncthreads();
    if (threadIdx.x == 0)
        g_ck[k] = (red[0] + red[1]) + (red[2] + red[3]);
}

// ---------------------------------------------------------------------------
// Main fused kernel: dist-GEMM -> exp -> h-GEMM -> reciprocal
// 128 CTAs x 128 threads, thread tile 4 rows x 8 k (phase B),
// 4 rows x 16 cols (phase C).
// ---------------------------------------------------------------------------
__global__ void __launch_bounds__(128, 1)
rbf_main_kernel(const float* __restrict__ x, float* __restrict__ out) {
    extern __shared__ float sm[];
    float* X2s = sm;                     // [Dn][XPITCH]
    float* Xs  = sm + Dn * XPITCH;       // [Dn][XPITCH]
    float* P   = sm + 2 * Dn * XPITCH;   // 16384 floats, multi-purpose

    const int tid = threadIdx.x;
    const int br0 = blockIdx.x * BM;

    // ---- Load X tile transposed, with squares --------------------------
    #pragma unroll
    for (int r = 0; r < BM; r++) {
        const float4 v = ((const float4*)(x + (size_t)(br0 + r) * Dn))[tid];
        const int d0 = tid * 4;
        Xs [(d0 + 0) * XPITCH + r] = v.x;  X2s[(d0 + 0) * XPITCH + r] = v.x * v.x;
        Xs [(d0 + 1) * XPITCH + r] = v.y;  X2s[(d0 + 1) * XPITCH + r] = v.y * v.y;
        Xs [(d0 + 2) * XPITCH + r] = v.z;  X2s[(d0 + 2) * XPITCH + r] = v.z * v.z;
        Xs [(d0 + 3) * XPITCH + r] = v.w;  X2s[(d0 + 3) * XPITCH + r] = v.w * v.w;
    }
    __syncthreads();

    const int kg = tid & 31;
    const int rg = tid >> 5;
    const int k0 = kg * 8;
    const int r0 = rg * 4;

    float acc[4][8];
    #pragma unroll
    for (int r = 0; r < 4; r++)
        #pragma unroll
        for (int kk = 0; kk < 8; kk++) acc[r][kk] = 0.0f;

    float* BWs = P;             // [DC][Kn]
    float* CWs = P + DC * Kn;   // [DC][Kn]

    // ---- Phase B: dist accumulation over d ------------------------------
    for (int dc = 0; dc < Dn; dc += DC) {
        const float4* bs = (const float4*)(g_bwt  + dc * Kn);
        const float4* cs = (const float4*)(g_cw2t + dc * Kn);
        float4* bd = (float4*)BWs;
        float4* cd = (float4*)CWs;
        #pragma unroll
        for (int j = 0; j < (DC * Kn / 4) / 128; j++) {   // 16 iters
            bd[tid + j * 128] = bs[tid + j * 128];
            cd[tid + j * 128] = cs[tid + j * 128];
        }
        __syncthreads();

        #pragma unroll 4
        for (int dd = 0; dd < DC; dd++) {
            const int d = dc + dd;
            float x2v[4], xv[4];
            #pragma unroll
            for (int r = 0; r < 4; r++) {
                x2v[r] = X2s[d * XPITCH + r0 + r];
                xv [r] = Xs [d * XPITCH + r0 + r];
            }
            const float4 b0 = *(const float4*)&BWs[dd * Kn + k0];
            const float4 b1 = *(const float4*)&BWs[dd * Kn + k0 + 4];
            const float4 c0 = *(const float4*)&CWs[dd * Kn + k0];
            const float4 c1 = *(const float4*)&CWs[dd * Kn + k0 + 4];
            const float bw[8] = {b0.x, b0.y, b0.z, b0.w, b1.x, b1.y, b1.z, b1.w};
            const float cw[8] = {c0.x, c0.y, c0.z, c0.w, c1.x, c1.y, c1.z, c1.w};
            #pragma unroll
            for (int r = 0; r < 4; r++) {
                #pragma unroll
                for (int kk = 0; kk < 8; kk++) {
                    acc[r][kk] = fmaf(bw[kk], x2v[r], acc[r][kk]);
                    acc[r][kk] = fmaf(cw[kk], xv[r],  acc[r][kk]);
                }
            }
        }
        __syncthreads();
    }

    // ---- exp epilogue into Rs (reuses P; phase-B readers already synced) -
    float ckv[8];
    #pragma unroll
    for (int kk = 0; kk < 8; kk++) ckv[kk] = g_ck[k0 + kk];

    float* Rs = P;  // [BM][Kn]
    #pragma unroll
    for (int r = 0; r < 4; r++) {
        float4 q0, q1;
        q0.x = expf(-0.5f * (acc[r][0] + ckv[0]));
        q0.y = expf(-0.5f * (acc[r][1] + ckv[1]));
        q0.z = expf(-0.5f * (acc[r][2] + ckv[2]));
        q0.w = expf(-0.5f * (acc[r][3] + ckv[3]));
        q1.x = expf(-0.5f * (acc[r][4] + ckv[4]));
        q1.y = expf(-0.5f * (acc[r][5] + ckv[5]));
        q1.z = expf(-0.5f * (acc[r][6] + ckv[6]));
        q1.w = expf(-0.5f * (acc[r][7] + ckv[7]));
        *(float4*)&Rs[(r0 + r) * Kn + k0]     = q0;
        *(float4*)&Rs[(r0 + r) * Kn + k0 + 4] = q1;
    }

    // ---- Phase C: h = Rs @ W, then out = 1/(h+eps) -----------------------
    float* Ws = P + BM * Kn;   // [KC][Dn]
    const int cg = tid & 31;
    const int cb = cg * 4;     // column base within each 128-col pass

    float hacc[4][16];
    #pragma unroll
    for (int r = 0; r < 4; r++)
        #pragma unroll
        for (int c = 0; c < 16; c++) hacc[r][c] = 0.0f;

    for (int kc = 0; kc < Kn; kc += KC) {
        const float4* ws = (const float4*)(g_w + kc * Dn);
        float4* wd = (float4*)Ws;
        #pragma unroll
        for (int j = 0; j < (KC * Dn / 4) / 128; j++)     // 16 iters
            wd[tid + j * 128] = ws[tid + j * 128];
        __syncthreads();   // also orders Rs stores before first reads

        #pragma unroll 2
        for (int kk = 0; kk < KC; kk++) {
            float rv[4];
            #pragma unroll
            for (int r = 0; r < 4; r++)
                rv[r] = Rs[(r0 + r) * Kn + kc + kk];
            #pragma unroll
            for (int p = 0; p < 4; p++) {
                const float4 w = *(const float4*)&Ws[kk * Dn + p * 128 + cb];
                #pragma unroll
                for (int r = 0; r < 4; r++) {
                    hacc[r][p * 4 + 0] = fmaf(rv[r], w.x, hacc[r][p * 4 + 0]);
                    hacc[r][p * 4 + 1] = fmaf(rv[r], w.y, hacc[r][p * 4 + 1]);
                    hacc[r][p * 4 + 2] = fmaf(rv[r], w.z, hacc[r][p * 4 + 2]);
                    hacc[r][p * 4 + 3] = fmaf(rv[r], w.w, hacc[r][p * 4 + 3]);
                }
            }
        }
        __syncthreads();
    }

    const float eps = 1e-3f;
    #pragma unroll
    for (int r = 0; r < 4; r++) {
        #pragma unroll
        for (int p = 0; p < 4; p++) {
            float4 o;
            o.x = 1.0f / (hacc[r][p * 4 + 0] + eps);
            o.y = 1.0f / (hacc[r][p * 4 + 1] + eps);
            o.z = 1.0f / (hacc[r][p * 4 + 2] + eps);
            o.w = 1.0f / (hacc[r][p * 4 + 3] + eps);
            *(float4*)(out + (size_t)(br0 + r0 + r) * Dn + p * 128 + cb) = o;
        }
    }
}

// ---------------------------------------------------------------------------
extern "C" void kernel_launch(void* const* d_in, const int* in_sizes, int n_in,
                              void* d_out, int out_size) {
    const float* x           = (const float*)d_in[0];
    const float* centers     = (const float*)d_in[1];
    const float* bandwidths  = (const float*)d_in[2];
    const float* raw_weights = (const float*)d_in[3];
    float* out = (float*)d_out;

    const int smem_bytes = (2 * Dn * XPITCH + 2 * DC * Kn) * (int)sizeof(float); // 139264
    static bool attr_set = false;
    if (!attr_set) {
        cudaFuncSetAttribute(rbf_main_kernel,
                             cudaFuncAttributeMaxDynamicSharedMemorySize, smem_bytes);
        attr_set = true;
    }

    prep_kernel<<<(Kn * Dn + 255) / 256, 256>>>(centers, bandwidths, raw_weights);
    prep_ck_kernel<<<Kn, 128>>>(centers, bandwidths);
    rbf_main_kernel<<<Bn / BM, 128, smem_bytes>>>(x, out);
}

// round 2
// speedup vs baseline: 1.0123x; 1.0123x over previous
#include <cuda_runtime.h>
#include <math.h>

// Problem shape (fixed by setup_inputs)
#define Bn 2048
#define Kn 256
#define Dn 512

#define BM 16      // rows per CTA  -> 128 CTAs
#define DC 32      // d-chunk staged in smem for phase B
#define KC 16      // k-chunk staged in smem for phase C
#define XPITCH 18  // padded pitch for transposed X tiles

typedef unsigned long long ull;

// __device__ scratch (allocation-free per harness rules)
__device__ float g_bwt [Dn * Kn];   // bw transposed: [d][k]
__device__ float g_cw2t[Dn * Kn];   // -2*bw*c transposed: [d][k]
__device__ float g_w   [Kn * Dn];   // softplus(raw_weights): [k][d]
__device__ float g_ck  [Kn];        // sum_d bw*c^2

// ---- packed f32x2 helpers (FFMA2: HW instruction ptxas won't emit) -------
__device__ __forceinline__ void ffma2(ull& d, ull a, ull b) {
    asm("fma.rn.f32x2 %0, %1, %2, %0;" : "+l"(d) : "l"(a), "l"(b));
}
__device__ __forceinline__ ull pack2(float x) {
    ull r; asm("mov.b64 %0, {%1, %1};" : "=l"(r) : "f"(x)); return r;
}
__device__ __forceinline__ void unpack2(float& lo, float& hi, ull v) {
    asm("mov.b64 {%0, %1}, %2;" : "=f"(lo), "=f"(hi) : "l"(v));
}

// ---------------------------------------------------------------------------
// Prep 1: transpose + precompute elementwise terms
// ---------------------------------------------------------------------------
__global__ void prep_kernel(const float* __restrict__ centers,
                            const float* __restrict__ bandwidths,
                            const float* __restrict__ raw_weights) {
    int i = blockIdx.x * blockDim.x + threadIdx.x;
    if (i >= Kn * Dn) return;
    int k = i >> 9;          // /Dn
    int d = i & (Dn - 1);
    float b = bandwidths[i];
    float c = centers[i];
    float r = raw_weights[i];
    g_bwt [d * Kn + k] = b;
    g_cw2t[d * Kn + k] = -2.0f * b * c;
    // fast softplus: max(r,0) + log(1 + exp(-|r|)), MUFU-based
    g_w[i] = fmaxf(r, 0.0f) + __logf(1.0f + __expf(-fabsf(r)));
}

// ---------------------------------------------------------------------------
// Prep 2: ck[k] = sum_d bw[k,d] * c[k,d]^2   (one block per k)
// ---------------------------------------------------------------------------
__global__ void prep_ck_kernel(const float* __restrict__ centers,
                               const float* __restrict__ bandwidths) {
    int k = blockIdx.x;
    float s = 0.0f;
    for (int d = threadIdx.x; d < Dn; d += blockDim.x) {
        float c = centers[k * Dn + d];
        s = fmaf(bandwidths[k * Dn + d] * c, c, s);
    }
    __shared__ float red[4];
    #pragma unroll
    for (int o = 16; o > 0; o >>= 1)
        s += __shfl_down_sync(0xffffffffu, s, o);
    if ((threadIdx.x & 31) == 0) red[threadIdx.x >> 5] = s;
    __syncthreads();
    if (threadIdx.x == 0)
        g_ck[k] = (red[0] + red[1]) + (red[2] + red[3]);
}

// ---------------------------------------------------------------------------
// Main fused kernel: dist-GEMM -> exp -> h-GEMM -> reciprocal (f32x2 packed)
// 128 CTAs x 128 threads, thread tile 4 rows x 8 k (phase B),
// 4 rows x 16 cols (phase C).
// ---------------------------------------------------------------------------
__global__ void __launch_bounds__(128, 1)
rbf_main_kernel(const float* __restrict__ x, float* __restrict__ out) {
    extern __shared__ float sm[];
    float* X2s = sm;                     // [Dn][XPITCH]
    float* Xs  = sm + Dn * XPITCH;       // [Dn][XPITCH]
    float* P   = sm + 2 * Dn * XPITCH;   // 16384 floats, multi-purpose

    const int tid = threadIdx.x;
    const int br0 = blockIdx.x * BM;

    // ---- Load X tile transposed, with squares --------------------------
    #pragma unroll
    for (int r = 0; r < BM; r++) {
        const float4 v = ((const float4*)(x + (size_t)(br0 + r) * Dn))[tid];
        const int d0 = tid * 4;
        Xs [(d0 + 0) * XPITCH + r] = v.x;  X2s[(d0 + 0) * XPITCH + r] = v.x * v.x;
        Xs [(d0 + 1) * XPITCH + r] = v.y;  X2s[(d0 + 1) * XPITCH + r] = v.y * v.y;
        Xs [(d0 + 2) * XPITCH + r] = v.z;  X2s[(d0 + 2) * XPITCH + r] = v.z * v.z;
        Xs [(d0 + 3) * XPITCH + r] = v.w;  X2s[(d0 + 3) * XPITCH + r] = v.w * v.w;
    }
    __syncthreads();

    const int kg = tid & 31;
    const int rg = tid >> 5;
    const int k0 = kg * 8;
    const int r0 = rg * 4;

    // packed accumulators: acc2[r][p] holds k pair (k0+2p, k0+2p+1)
    ull acc2[4][4];
    #pragma unroll
    for (int r = 0; r < 4; r++)
        #pragma unroll
        for (int p = 0; p < 4; p++) acc2[r][p] = 0ull;

    float* BWs = P;             // [DC][Kn]
    float* CWs = P + DC * Kn;   // [DC][Kn]

    // ---- Phase B: dist accumulation over d ------------------------------
    for (int dc = 0; dc < Dn; dc += DC) {
        const float4* bs = (const float4*)(g_bwt  + dc * Kn);
        const float4* cs = (const float4*)(g_cw2t + dc * Kn);
        float4* bd = (float4*)BWs;
        float4* cd = (float4*)CWs;
        #pragma unroll
        for (int j = 0; j < (DC * Kn / 4) / 128; j++) {   // 16 iters
            bd[tid + j * 128] = bs[tid + j * 128];
            cd[tid + j * 128] = cs[tid + j * 128];
        }
        __syncthreads();

        #pragma unroll 4
        for (int dd = 0; dd < DC; dd++) {
            const int d = dc + dd;
            ull x2p[4], xp[4];
            #pragma unroll
            for (int r = 0; r < 4; r++) {
                x2p[r] = pack2(X2s[d * XPITCH + r0 + r]);
                xp [r] = pack2(Xs [d * XPITCH + r0 + r]);
            }
            const ulonglong2 B0 = *(const ulonglong2*)&BWs[dd * Kn + k0];
            const ulonglong2 B1 = *(const ulonglong2*)&BWs[dd * Kn + k0 + 4];
            const ulonglong2 C0 = *(const ulonglong2*)&CWs[dd * Kn + k0];
            const ulonglong2 C1 = *(const ulonglong2*)&CWs[dd * Kn + k0 + 4];
            const ull bw[4] = {B0.x, B0.y, B1.x, B1.y};
            const ull cw[4] = {C0.x, C0.y, C1.x, C1.y};
            #pragma unroll
            for (int r = 0; r < 4; r++) {
                #pragma unroll
                for (int p = 0; p < 4; p++) {
                    ffma2(acc2[r][p], bw[p], x2p[r]);
                    ffma2(acc2[r][p], cw[p], xp[r]);
                }
            }
        }
        __syncthreads();
    }

    // ---- exp epilogue into Rs (reuses P) ---------------------------------
    float ckv[8];
    #pragma unroll
    for (int kk = 0; kk < 8; kk++) ckv[kk] = g_ck[k0 + kk];

    float* Rs = P;  // [BM][Kn]
    #pragma unroll
    for (int r = 0; r < 4; r++) {
        float a[8];
        #pragma unroll
        for (int p = 0; p < 4; p++) unpack2(a[2 * p], a[2 * p + 1], acc2[r][p]);
        float4 q0, q1;
        q0.x = __expf(-0.5f * (a[0] + ckv[0]));
        q0.y = __expf(-0.5f * (a[1] + ckv[1]));
        q0.z = __expf(-0.5f * (a[2] + ckv[2]));
        q0.w = __expf(-0.5f * (a[3] + ckv[3]));
        q1.x = __expf(-0.5f * (a[4] + ckv[4]));
        q1.y = __expf(-0.5f * (a[5] + ckv[5]));
        q1.z = __expf(-0.5f * (a[6] + ckv[6]));
        q1.w = __expf(-0.5f * (a[7] + ckv[7]));
        *(float4*)&Rs[(r0 + r) * Kn + k0]     = q0;
        *(float4*)&Rs[(r0 + r) * Kn + k0 + 4] = q1;
    }

    // ---- Phase C: h = Rs @ W, then out = 1/(h+eps) -----------------------
    float* Ws = P + BM * Kn;   // [KC][Dn]
    const int cg = tid & 31;
    const int cb = cg * 4;     // column base within each 128-col pass

    // hacc2[r][q]: q indexes 8 col-pairs (4 passes x 2 pairs)
    ull hacc2[4][8];
    #pragma unroll
    for (int r = 0; r < 4; r++)
        #pragma unroll
        for (int q = 0; q < 8; q++) hacc2[r][q] = 0ull;

    for (int kc = 0; kc < Kn; kc += KC) {
        const float4* ws = (const float4*)(g_w + kc * Dn);
        float4* wd = (float4*)Ws;
        #pragma unroll
        for (int j = 0; j < (KC * Dn / 4) / 128; j++)     // 16 iters
            wd[tid + j * 128] = ws[tid + j * 128];
        __syncthreads();   // also orders Rs stores before first reads

        #pragma unroll 2
        for (int kk = 0; kk < KC; kk++) {
            ull rr[4];
            #pragma unroll
            for (int r = 0; r < 4; r++)
                rr[r] = pack2(Rs[(r0 + r) * Kn + kc + kk]);
            #pragma unroll
            for (int p = 0; p < 4; p++) {
                const ulonglong2 W2 = *(const ulonglong2*)&Ws[kk * Dn + p * 128 + cb];
                #pragma unroll
                for (int r = 0; r < 4; r++) {
                    ffma2(hacc2[r][p * 2 + 0], rr[r], W2.x);
                    ffma2(hacc2[r][p * 2 + 1], rr[r], W2.y);
                }
            }
        }
        __syncthreads();
    }

    const float eps = 1e-3f;
    #pragma unroll
    for (int r = 0; r < 4; r++) {
        #pragma unroll
        for (int p = 0; p < 4; p++) {
            float h0, h1, h2, h3;
            unpack2(h0, h1, hacc2[r][p * 2 + 0]);
            unpack2(h2, h3, hacc2[r][p * 2 + 1]);
            float4 o;
            o.x = __fdividef(1.0f, h0 + eps);
            o.y = __fdividef(1.0f, h1 + eps);
            o.z = __fdividef(1.0f, h2 + eps);
            o.w = __fdividef(1.0f, h3 + eps);
            *(float4*)(out + (size_t)(br0 + r0 + r) * Dn + p * 128 + cb) = o;
        }
    }
}

// ---------------------------------------------------------------------------
extern "C" void kernel_launch(void* const* d_in, const int* in_sizes, int n_in,
                              void* d_out, int out_size) {
    const float* x           = (const float*)d_in[0];
    const float* centers     = (const float*)d_in[1];
    const float* bandwidths  = (const float*)d_in[2];
    const float* raw_weights = (const float*)d_in[3];
    float* out = (float*)d_out;

    const int smem_bytes = (2 * Dn * XPITCH + 2 * DC * Kn) * (int)sizeof(float); // 139264
    static bool attr_set = false;
    if (!attr_set) {
        cudaFuncSetAttribute(rbf_main_kernel,
                             cudaFuncAttributeMaxDynamicSharedMemorySize, smem_bytes);
        attr_set = true;
    }

    prep_kernel<<<(Kn * Dn + 255) / 256, 256>>>(centers, bandwidths, raw_weights);
    prep_ck_kernel<<<Kn, 128>>>(centers, bandwidths);
    rbf_main_kernel<<<Bn / BM, 128, smem_bytes>>>(x, out);
}

// round 4
// speedup vs baseline: 3.8957x; 3.8484x over previous
#include <cuda_runtime.h>
#include <cuda_bf16.h>
#include <cstdint>
#include <math.h>

// Problem shape (fixed by setup_inputs)
#define Bn 2048
#define Kn 256
#define Dn 512

// bf16 staging buffers (__device__ globals: allocation-free)
__device__ __nv_bfloat16 g_abig[Bn * 1024];  // [b][ 0..511: x^2 | 512..1023: x ]
__device__ __nv_bfloat16 g_bmat[Kn * 1024];  // [k][ 0..511: bw  | 512..1023: -2*bw*c ]
__device__ __nv_bfloat16 g_rbf [Bn * Kn];    // rbf result, K-major for GEMM2
__device__ __nv_bfloat16 g_wt  [Dn * Kn];    // softplus(W) transposed: [d][k]
__device__ float         g_ck  [Kn];         // sum_d bw*c^2

// ---------------------------------------------------------------------------
// Helpers (arch-generic: ldmatrix / mma.sync / cp.async only — NO tcgen05,
// the harness PTX stage targets plain compute_103)
// ---------------------------------------------------------------------------
__device__ __forceinline__ uint32_t s2u(const void* p) {
    uint32_t a;
    asm("{ .reg .u64 t; cvta.to.shared.u64 t, %1; cvt.u32.u64 %0, t; }"
        : "=r"(a) : "l"(p));
    return a;
}
#define SW128(o) ((o) ^ (((o) >> 3) & 0x70))

__device__ __forceinline__ void cp16(uint32_t s, const void* g) {
    asm volatile("cp.async.cg.shared.global [%0], [%1], 16;" :: "r"(s), "l"(g));
}

__device__ __forceinline__ void ldsm4(uint32_t* r, uint32_t addr) {
    asm volatile("ldmatrix.sync.aligned.m8n8.x4.shared.b16 {%0,%1,%2,%3}, [%4];"
                 : "=r"(r[0]), "=r"(r[1]), "=r"(r[2]), "=r"(r[3]) : "r"(addr));
}

__device__ __forceinline__ void mma16816(float* c, const uint32_t* a, const uint32_t* b) {
    asm volatile(
        "mma.sync.aligned.m16n8k16.row.col.f32.bf16.bf16.f32 "
        "{%0,%1,%2,%3}, {%4,%5,%6,%7}, {%8,%9}, {%0,%1,%2,%3};"
        : "+f"(c[0]), "+f"(c[1]), "+f"(c[2]), "+f"(c[3])
        : "r"(a[0]), "r"(a[1]), "r"(a[2]), "r"(a[3]), "r"(b[0]), "r"(b[1]));
}

// ---------------------------------------------------------------------------
// Prep kernels
// ---------------------------------------------------------------------------
__global__ void prepA(const float* __restrict__ x) {
    int i = blockIdx.x * blockDim.x + threadIdx.x;     // over Bn*Dn/4
    float4 v = ((const float4*)x)[i];
    int e4 = i * 4;
    int row = e4 >> 9;
    int d = e4 & 511;
    __nv_bfloat162* ps = (__nv_bfloat162*)&g_abig[row * 1024 + d];
    ps[0] = __floats2bfloat162_rn(v.x * v.x, v.y * v.y);
    ps[1] = __floats2bfloat162_rn(v.z * v.z, v.w * v.w);
    __nv_bfloat162* px = (__nv_bfloat162*)&g_abig[row * 1024 + 512 + d];
    px[0] = __floats2bfloat162_rn(v.x, v.y);
    px[1] = __floats2bfloat162_rn(v.z, v.w);
}

__global__ void prepB(const float* __restrict__ bw, const float* __restrict__ c) {
    int i = blockIdx.x * blockDim.x + threadIdx.x;     // over Kn*Dn/4
    float4 b = ((const float4*)bw)[i];
    float4 cc = ((const float4*)c)[i];
    int e4 = i * 4;
    int k = e4 >> 9;
    int d = e4 & 511;
    __nv_bfloat162* pb = (__nv_bfloat162*)&g_bmat[k * 1024 + d];
    pb[0] = __floats2bfloat162_rn(b.x, b.y);
    pb[1] = __floats2bfloat162_rn(b.z, b.w);
    __nv_bfloat162* pc = (__nv_bfloat162*)&g_bmat[k * 1024 + 512 + d];
    pc[0] = __floats2bfloat162_rn(-2.0f * b.x * cc.x, -2.0f * b.y * cc.y);
    pc[1] = __floats2bfloat162_rn(-2.0f * b.z * cc.z, -2.0f * b.w * cc.w);
}

// softplus + transpose: g_wt[d][k] = softplus(raw[k][d])
__global__ void prepW(const float* __restrict__ raw) {
    __shared__ float t[32][33];
    const int d0 = blockIdx.x * 32, k0 = blockIdx.y * 32;
    const int tx = threadIdx.x, ty = threadIdx.y;      // (32, 8)
    #pragma unroll
    for (int j = 0; j < 4; j++) {
        int k = k0 + ty + j * 8;
        float r = raw[k * Dn + d0 + tx];
        t[ty + j * 8][tx] = fmaxf(r, 0.0f) + __logf(1.0f + __expf(-fabsf(r)));
    }
    __syncthreads();
    #pragma unroll
    for (int j = 0; j < 4; j++) {
        int d = d0 + ty + j * 8;
        g_wt[d * Kn + k0 + tx] = __float2bfloat16(t[tx][ty + j * 8]);
    }
}

__global__ void prep_ck(const float* __restrict__ centers,
                        const float* __restrict__ bandwidths) {
    int k = blockIdx.x;
    float s = 0.0f;
    for (int d = threadIdx.x; d < Dn; d += blockDim.x) {
        float c = centers[k * Dn + d];
        s = fmaf(bandwidths[k * Dn + d] * c, c, s);
    }
    __shared__ float red[4];
    #pragma unroll
    for (int o = 16; o > 0; o >>= 1)
        s += __shfl_down_sync(0xffffffffu, s, o);
    if ((threadIdx.x & 31) == 0) red[threadIdx.x >> 5] = s;
    __syncthreads();
    if (threadIdx.x == 0)
        g_ck[k] = (red[0] + red[1]) + (red[2] + red[3]);
}

// ---------------------------------------------------------------------------
// HMMA bf16 GEMM: C[64,64] fp32 = A[64,Kd] x B[64,Kd]^T  (both K-major)
// 128 threads / 4 warps, warp tile 32x32, K staged 64 (SW128, cp.async x2).
// ISG2=false: rbf epilogue (exp -> bf16 g_rbf). ISG2=true: 1/(h+eps) -> out.
// ---------------------------------------------------------------------------
#define STAGE_BYTES 16384     // A 8K + B 8K
#define SMEMSZ (2 * STAGE_BYTES + 256)

template<int LDA, int LDB, int NCHUNK, bool ISG2>
__global__ void __launch_bounds__(128)
gemm_kern(const __nv_bfloat16* __restrict__ A,
          const __nv_bfloat16* __restrict__ Bm,
          float* __restrict__ out) {
    extern __shared__ char sm[];
    const uint32_t T0 = s2u(sm);
    const int tid = threadIdx.x, wid = tid >> 5, l = tid & 31;
    const int m0 = blockIdx.x * 64, n0 = blockIdx.y * 64;
    const int wm = wid & 1, wn = wid >> 1;

    // ldmatrix lane-derived constants
    const int lr  = l & 7, sel = l >> 3;
    const int a_row = wm * 32 + (sel & 1) * 8 + lr;        // + mi*16
    const uint32_t a_kb = (uint32_t)((sel >> 1) * 16);     // + ks*32
    const int b_row = wn * 32 + (sel >> 1) * 8 + lr;       // + bi*16
    const uint32_t b_kb = (uint32_t)((sel & 1) * 16);

    #define LOAD_CHUNK(ch, s) do {                                           \
        uint32_t _sa = T0 + (s) * STAGE_BYTES;                               \
        const __nv_bfloat16* _ga = A  + (size_t)m0 * LDA + (ch) * 64;        \
        const __nv_bfloat16* _gb = Bm + (size_t)n0 * LDB + (ch) * 64;        \
        _Pragma("unroll")                                                    \
        for (int q = 0; q < 4; q++) {                                        \
            int u = tid + q * 128;                                           \
            int r = u >> 3, cc = u & 7;                                      \
            uint32_t off = SW128((uint32_t)(r * 128 + cc * 16));             \
            cp16(_sa        + off, _ga + (size_t)r * LDA + cc * 8);          \
            cp16(_sa + 8192 + off, _gb + (size_t)r * LDB + cc * 8);          \
        }                                                                    \
        asm volatile("cp.async.commit_group;");                              \
    } while (0)

    float acc[2][4][4];
    #pragma unroll
    for (int mi = 0; mi < 2; mi++)
        #pragma unroll
        for (int nj = 0; nj < 4; nj++)
            #pragma unroll
            for (int e = 0; e < 4; e++) acc[mi][nj][e] = 0.0f;

    LOAD_CHUNK(0, 0);
    LOAD_CHUNK(1, 1);

    for (int i = 0; i < NCHUNK; i++) {
        const int s = i & 1;
        if (i + 1 < NCHUNK) asm volatile("cp.async.wait_group 1;");
        else                asm volatile("cp.async.wait_group 0;");
        __syncthreads();

        const uint32_t sa  = T0 + s * STAGE_BYTES;
        const uint32_t sbb = sa + 8192;
        #pragma unroll
        for (int ks = 0; ks < 4; ks++) {
            uint32_t a[2][4], b[2][4];
            #pragma unroll
            for (int mi = 0; mi < 2; mi++)
                ldsm4(a[mi], sa + SW128((uint32_t)((a_row + mi * 16) * 128)
                                        + (uint32_t)(ks * 32) + a_kb));
            #pragma unroll
            for (int bi = 0; bi < 2; bi++)
                ldsm4(b[bi], sbb + SW128((uint32_t)((b_row + bi * 16) * 128)
                                         + (uint32_t)(ks * 32) + b_kb));
            #pragma unroll
            for (int mi = 0; mi < 2; mi++)
                #pragma unroll
                for (int nj = 0; nj < 4; nj++)
                    mma16816(acc[mi][nj], a[mi], &b[nj >> 1][(nj & 1) * 2]);
        }
        __syncthreads();                     // stage s free to overwrite
        if (i + 2 < NCHUNK) LOAD_CHUNK(i + 2, s);
    }
    #undef LOAD_CHUNK

    // ---- Epilogue -------------------------------------------------------
    const int erow  = m0 + wm * 32 + (l >> 2);
    const int ecol0 = wn * 32 + 2 * (l & 3);

    if (!ISG2) {
        float* sck = (float*)(sm + 2 * STAGE_BYTES);
        if (tid < 64) sck[tid] = g_ck[n0 + tid];
        __syncthreads();
        #pragma unroll
        for (int mi = 0; mi < 2; mi++) {
            #pragma unroll
            for (int nj = 0; nj < 4; nj++) {
                const int col = ecol0 + nj * 8;
                const float ck0 = sck[col], ck1 = sck[col + 1];
                const int r = erow + mi * 16;
                float v0 = __expf(-0.5f * (acc[mi][nj][0] + ck0));
                float v1 = __expf(-0.5f * (acc[mi][nj][1] + ck1));
                float v2 = __expf(-0.5f * (acc[mi][nj][2] + ck0));
                float v3 = __expf(-0.5f * (acc[mi][nj][3] + ck1));
                __nv_bfloat162 p0 = __floats2bfloat162_rn(v0, v1);
                __nv_bfloat162 p1 = __floats2bfloat162_rn(v2, v3);
                *(__nv_bfloat162*)&g_rbf[(size_t)r * Kn + n0 + col]       = p0;
                *(__nv_bfloat162*)&g_rbf[(size_t)(r + 8) * Kn + n0 + col] = p1;
            }
        }
    } else {
        const float eps = 1e-3f;
        #pragma unroll
        for (int mi = 0; mi < 2; mi++) {
            #pragma unroll
            for (int nj = 0; nj < 4; nj++) {
                const int col = n0 + ecol0 + nj * 8;
                const int r = erow + mi * 16;
                float2 o0, o1;
                o0.x = __fdividef(1.0f, acc[mi][nj][0] + eps);
                o0.y = __fdividef(1.0f, acc[mi][nj][1] + eps);
                o1.x = __fdividef(1.0f, acc[mi][nj][2] + eps);
                o1.y = __fdividef(1.0f, acc[mi][nj][3] + eps);
                *(float2*)(out + (size_t)r * Dn + col)       = o0;
                *(float2*)(out + (size_t)(r + 8) * Dn + col) = o1;
            }
        }
    }
}

// ---------------------------------------------------------------------------
extern "C" void kernel_launch(void* const* d_in, const int* in_sizes, int n_in,
                              void* d_out, int out_size) {
    const float* x           = (const float*)d_in[0];
    const float* centers     = (const float*)d_in[1];
    const float* bandwidths  = (const float*)d_in[2];
    const float* raw_weights = (const float*)d_in[3];
    float* out = (float*)d_out;

    static const __nv_bfloat16 *pA = nullptr, *pB = nullptr, *pR = nullptr, *pW = nullptr;
    if (!pA) {
        void* p;
        cudaGetSymbolAddress(&p, g_abig); pA = (const __nv_bfloat16*)p;
        cudaGetSymbolAddress(&p, g_bmat); pB = (const __nv_bfloat16*)p;
        cudaGetSymbolAddress(&p, g_rbf);  pR = (const __nv_bfloat16*)p;
        cudaGetSymbolAddress(&p, g_wt);   pW = (const __nv_bfloat16*)p;
    }

    prepA<<<(Bn * Dn / 4) / 256, 256>>>(x);
    prepB<<<(Kn * Dn / 4) / 256, 256>>>(bandwidths, centers);
    prepW<<<dim3(Dn / 32, Kn / 32), dim3(32, 8)>>>(raw_weights);
    prep_ck<<<Kn, 128>>>(centers, bandwidths);

    // G1: dist GEMM (M=2048, N=256, K=1024) -> rbf (bf16)
    gemm_kern<1024, 1024, 16, false><<<dim3(Bn / 64, Kn / 64), 128, SMEMSZ>>>(pA, pB, nullptr);
    // G2: h GEMM (M=2048, N=512, K=256) -> out = 1/(h+eps)
    gemm_kern<256, 256, 4, true><<<dim3(Bn / 64, Dn / 64), 128, SMEMSZ>>>(pR, pW, out);
}

// round 6
// speedup vs baseline: 4.6683x; 1.1983x over previous
#include <cuda_runtime.h>
#include <cuda_bf16.h>
#include <cstdint>
#include <math.h>

// Problem shape (fixed by setup_inputs)
#define Bn 2048
#define Kn 256
#define Dn 512

// bf16 staging buffers (__device__ globals: allocation-free)
__device__ __nv_bfloat16 g_abig[Bn * 1024];  // [b][ 0..511: x^2 | 512..1023: x ]
__device__ __nv_bfloat16 g_bmat[Kn * 1024];  // [k][ 0..511: bw  | 512..1023: -2*bw*c ]
__device__ __nv_bfloat16 g_rbf [Bn * Kn];    // rbf result, K-major for GEMM2
__device__ __nv_bfloat16 g_wt  [Dn * Kn];    // softplus(W) transposed: [d][k]
__device__ float         g_ck  [Kn];         // sum_d bw*c^2

// ---------------------------------------------------------------------------
// Helpers (arch-generic: ldmatrix / mma.sync / cp.async — NO tcgen05, the
// harness PTX stage targets plain compute_103)
// ---------------------------------------------------------------------------
__device__ __forceinline__ uint32_t s2u(const void* p) {
    uint32_t a;
    asm("{ .reg .u64 t; cvta.to.shared.u64 t, %1; cvt.u32.u64 %0, t; }"
        : "=r"(a) : "l"(p));
    return a;
}
#define SW128(o) ((o) ^ (((o) >> 3) & 0x70))

__device__ __forceinline__ void cp16(uint32_t s, const void* g) {
    asm volatile("cp.async.cg.shared.global [%0], [%1], 16;" :: "r"(s), "l"(g));
}

__device__ __forceinline__ void ldsm4(uint32_t* r, uint32_t addr) {
    asm volatile("ldmatrix.sync.aligned.m8n8.x4.shared.b16 {%0,%1,%2,%3}, [%4];"
                 : "=r"(r[0]), "=r"(r[1]), "=r"(r[2]), "=r"(r[3]) : "r"(addr));
}

__device__ __forceinline__ void mma16816(float* c, const uint32_t* a, const uint32_t* b) {
    asm volatile(
        "mma.sync.aligned.m16n8k16.row.col.f32.bf16.bf16.f32 "
        "{%0,%1,%2,%3}, {%4,%5,%6,%7}, {%8,%9}, {%0,%1,%2,%3};"
        : "+f"(c[0]), "+f"(c[1]), "+f"(c[2]), "+f"(c[3])
        : "r"(a[0]), "r"(a[1]), "r"(a[2]), "r"(a[3]), "r"(b[0]), "r"(b[1]));
}

// ---------------------------------------------------------------------------
// Fused prep: one launch.
//   blocks [0,1024):    A-matrix build (x^2 | x) -> bf16
//   blocks [1024,1152): B-matrix build (bw | -2bw*c) -> bf16, + ck reduction
//   blocks [1152,1280): W softplus + transpose -> bf16
// ---------------------------------------------------------------------------
__global__ void __launch_bounds__(256)
prep_all(const float* __restrict__ x, const float* __restrict__ centers,
         const float* __restrict__ bandwidths, const float* __restrict__ raw) {
    const int bid = blockIdx.x, tid = threadIdx.x;

    if (bid < 1024) {                        // ---- prepA ----
        const int i = bid * 256 + tid;       // float4 over Bn*Dn/4
        float4 v = ((const float4*)x)[i];
        const int e4 = i * 4;
        const int row = e4 >> 9;
        const int d = e4 & 511;
        __nv_bfloat162* ps = (__nv_bfloat162*)&g_abig[row * 1024 + d];
        ps[0] = __floats2bfloat162_rn(v.x * v.x, v.y * v.y);
        ps[1] = __floats2bfloat162_rn(v.z * v.z, v.w * v.w);
        __nv_bfloat162* px = (__nv_bfloat162*)&g_abig[row * 1024 + 512 + d];
        px[0] = __floats2bfloat162_rn(v.x, v.y);
        px[1] = __floats2bfloat162_rn(v.z, v.w);
        return;
    }

    if (bid < 1152) {                        // ---- prepB + ck ----
        const int kb = (bid - 1024) * 2;     // 2 k-rows per block
        const int kloc = tid >> 7;           // 0/1
        const int j = tid & 127;             // float4 within row
        const int k = kb + kloc;
        const int base = k * 512 + j * 4;    // element index
        float4 b = *(const float4*)&bandwidths[base];
        float4 cc = *(const float4*)&centers[base];
        const int d = j * 4;
        __nv_bfloat162* pb = (__nv_bfloat162*)&g_bmat[k * 1024 + d];
        pb[0] = __floats2bfloat162_rn(b.x, b.y);
        pb[1] = __floats2bfloat162_rn(b.z, b.w);
        __nv_bfloat162* pc = (__nv_bfloat162*)&g_bmat[k * 1024 + 512 + d];
        pc[0] = __floats2bfloat162_rn(-2.0f * b.x * cc.x, -2.0f * b.y * cc.y);
        pc[1] = __floats2bfloat162_rn(-2.0f * b.z * cc.z, -2.0f * b.w * cc.w);
        // ck partial: sum bw*c^2 over this thread's 4 elems
        float s = b.x * cc.x * cc.x + b.y * cc.y * cc.y
                + b.z * cc.z * cc.z + b.w * cc.w * cc.w;
        #pragma unroll
        for (int o = 16; o > 0; o >>= 1)
            s += __shfl_down_sync(0xffffffffu, s, o);
        __shared__ float red[8];
        if ((tid & 31) == 0) red[tid >> 5] = s;
        __syncthreads();
        if ((tid & 127) == 0) {
            const int rb = kloc * 4;
            g_ck[k] = (red[rb] + red[rb + 1]) + (red[rb + 2] + red[rb + 3]);
        }
        return;
    }

    {                                        // ---- prepW ----
        const int t2 = bid - 1152;
        const int d0 = (t2 & 15) * 32, k0 = (t2 >> 4) * 32;
        const int tx = tid & 31, ty = tid >> 5;          // 32 x 8
        __shared__ float t[32][33];
        #pragma unroll
        for (int jj = 0; jj < 4; jj++) {
            int k = k0 + ty + jj * 8;
            float r = raw[k * Dn + d0 + tx];
            t[ty + jj * 8][tx] = fmaxf(r, 0.0f) + __logf(1.0f + __expf(-fabsf(r)));
        }
        __syncthreads();
        #pragma unroll
        for (int jj = 0; jj < 4; jj++) {
            int d = d0 + ty + jj * 8;
            g_wt[d * Kn + k0 + tx] = __float2bfloat16(t[tx][ty + jj * 8]);
        }
    }
}

// ---------------------------------------------------------------------------
// HMMA bf16 GEMM: C[64,64] fp32 = A[64,Kd] x B[64,Kd]^T  (both K-major)
// 128 threads / 4 warps, warp tile 32x32, K staged 64 wide (SW128),
// 3-stage cp.async pipeline, one __syncthreads per chunk.
// Sources are the __device__ globals (no host symbol lookup needed):
//   ISG2=false: A=g_abig (LD 1024), B=g_bmat (LD 1024), 16 chunks,
//               epilogue exp(-0.5*(d+ck)) -> bf16 g_rbf
//   ISG2=true:  A=g_rbf (LD 256),  B=g_wt  (LD 256),   4 chunks,
//               epilogue 1/(h+eps) -> out
// SMEM = 3*16384 = 49152 bytes exactly (default limit, no attribute call);
// the epilogue ck buffer overlaps stage 0 (dead by then, barrier-guarded).
// ---------------------------------------------------------------------------
#define STAGE_BYTES 16384     // A 8K + B 8K
#define NSTAGE 3
#define SMEMSZ (NSTAGE * STAGE_BYTES)

template<bool ISG2>
__global__ void __launch_bounds__(128)
gemm_kern(float* __restrict__ out) {
    constexpr int LDA    = ISG2 ? 256 : 1024;
    constexpr int LDB    = ISG2 ? 256 : 1024;
    constexpr int NCHUNK = ISG2 ? 4   : 16;
    const __nv_bfloat16* __restrict__ A  = ISG2 ? g_rbf : g_abig;
    const __nv_bfloat16* __restrict__ Bm = ISG2 ? g_wt  : g_bmat;

    extern __shared__ char sm[];
    const uint32_t T0 = s2u(sm);
    const int tid = threadIdx.x, wid = tid >> 5, l = tid & 31;
    const int m0 = blockIdx.x * 64, n0 = blockIdx.y * 64;
    const int wm = wid & 1, wn = wid >> 1;

    // ldmatrix lane-derived constants
    const int lr  = l & 7, sel = l >> 3;
    const int a_row = wm * 32 + (sel & 1) * 8 + lr;        // + mi*16
    const uint32_t a_kb = (uint32_t)((sel >> 1) * 16);     // + ks*32
    const int b_row = wn * 32 + (sel >> 1) * 8 + lr;       // + bi*16
    const uint32_t b_kb = (uint32_t)((sel & 1) * 16);

    #define LOAD_CHUNK(ch, s) do {                                           \
        uint32_t _sa = T0 + (s) * STAGE_BYTES;                               \
        const __nv_bfloat16* _ga = A  + (size_t)m0 * LDA + (ch) * 64;        \
        const __nv_bfloat16* _gb = Bm + (size_t)n0 * LDB + (ch) * 64;        \
        _Pragma("unroll")                                                    \
        for (int q = 0; q < 4; q++) {                                        \
            int u = tid + q * 128;                                           \
            int r = u >> 3, cc = u & 7;                                      \
            uint32_t off = SW128((uint32_t)(r * 128 + cc * 16));             \
            cp16(_sa        + off, _ga + (size_t)r * LDA + cc * 8);          \
            cp16(_sa + 8192 + off, _gb + (size_t)r * LDB + cc * 8);          \
        }                                                                    \
        asm volatile("cp.async.commit_group;");                              \
    } while (0)

    float acc[2][4][4];
    #pragma unroll
    for (int mi = 0; mi < 2; mi++)
        #pragma unroll
        for (int nj = 0; nj < 4; nj++)
            #pragma unroll
            for (int e = 0; e < 4; e++) acc[mi][nj][e] = 0.0f;

    LOAD_CHUNK(0, 0);
    LOAD_CHUNK(1, 1);

    for (int i = 0; i < NCHUNK; i++) {
        const int s = i % NSTAGE;
        if (i < NCHUNK - 1) asm volatile("cp.async.wait_group 1;");
        else                asm volatile("cp.async.wait_group 0;");
        // One barrier per chunk: (a) stage s visible to all warps,
        // (b) all warps done with chunk i-1, so stage (i+2)%3 == (i-1)%3
        // is safe to overwrite.
        __syncthreads();
        if (i + 2 < NCHUNK) LOAD_CHUNK(i + 2, (i + 2) % NSTAGE);

        const uint32_t sa  = T0 + s * STAGE_BYTES;
        const uint32_t sbb = sa + 8192;
        #pragma unroll
        for (int ks = 0; ks < 4; ks++) {
            uint32_t a[2][4], b[2][4];
            #pragma unroll
            for (int mi = 0; mi < 2; mi++)
                ldsm4(a[mi], sa + SW128((uint32_t)((a_row + mi * 16) * 128)
                                        + (uint32_t)(ks * 32) + a_kb));
            #pragma unroll
            for (int bi = 0; bi < 2; bi++)
                ldsm4(b[bi], sbb + SW128((uint32_t)((b_row + bi * 16) * 128)
                                         + (uint32_t)(ks * 32) + b_kb));
            #pragma unroll
            for (int mi = 0; mi < 2; mi++)
                #pragma unroll
                for (int nj = 0; nj < 4; nj++)
                    mma16816(acc[mi][nj], a[mi], &b[nj >> 1][(nj & 1) * 2]);
        }
    }
    #undef LOAD_CHUNK

    // ---- Epilogue -------------------------------------------------------
    const int erow  = m0 + wm * 32 + (l >> 2);
    const int ecol0 = wn * 32 + 2 * (l & 3);

    if (!ISG2) {
        float* sck = (float*)sm;              // overlaps stage 0 (dead now)
        __syncthreads();                      // all stage reads complete
        if (tid < 64) sck[tid] = g_ck[n0 + tid];
        __syncthreads();
        #pragma unroll
        for (int mi = 0; mi < 2; mi++) {
            #pragma unroll
            for (int nj = 0; nj < 4; nj++) {
                const int col = ecol0 + nj * 8;
                const float ck0 = sck[col], ck1 = sck[col + 1];
                const int r = erow + mi * 16;
                float v0 = __expf(-0.5f * (acc[mi][nj][0] + ck0));
                float v1 = __expf(-0.5f * (acc[mi][nj][1] + ck1));
                float v2 = __expf(-0.5f * (acc[mi][nj][2] + ck0));
                float v3 = __expf(-0.5f * (acc[mi][nj][3] + ck1));
                __nv_bfloat162 p0 = __floats2bfloat162_rn(v0, v1);
                __nv_bfloat162 p1 = __floats2bfloat162_rn(v2, v3);
                *(__nv_bfloat162*)&g_rbf[(size_t)r * Kn + n0 + col]       = p0;
                *(__nv_bfloat162*)&g_rbf[(size_t)(r + 8) * Kn + n0 + col] = p1;
            }
        }
    } else {
        const float eps = 1e-3f;
        #pragma unroll
        for (int mi = 0; mi < 2; mi++) {
            #pragma unroll
            for (int nj = 0; nj < 4; nj++) {
                const int col = n0 + ecol0 + nj * 8;
                const int r = erow + mi * 16;
                float2 o0, o1;
                o0.x = __fdividef(1.0f, acc[mi][nj][0] + eps);
                o0.y = __fdividef(1.0f, acc[mi][nj][1] + eps);
                o1.x = __fdividef(1.0f, acc[mi][nj][2] + eps);
                o1.y = __fdividef(1.0f, acc[mi][nj][3] + eps);
                *(float2*)(out + (size_t)r * Dn + col)       = o0;
                *(float2*)(out + (size_t)(r + 8) * Dn + col) = o1;
            }
        }
    }
}

// ---------------------------------------------------------------------------
extern "C" void kernel_launch(void* const* d_in, const int* in_sizes, int n_in,
                              void* d_out, int out_size) {
    const float* x           = (const float*)d_in[0];
    const float* centers     = (const float*)d_in[1];
    const float* bandwidths  = (const float*)d_in[2];
    const float* raw_weights = (const float*)d_in[3];
    float* out = (float*)d_out;

    prep_all<<<1280, 256>>>(x, centers, bandwidths, raw_weights);

    // G1: dist GEMM (M=2048, N=256, K=1024) -> rbf (bf16)
    gemm_kern<false><<<dim3(Bn / 64, Kn / 64), 128, SMEMSZ>>>(nullptr);
    // G2: h GEMM (M=2048, N=512, K=256) -> out = 1/(h+eps)
    gemm_kern<true><<<dim3(Bn / 64, Dn / 64), 128, SMEMSZ>>>(out);
}

// round 7
// speedup vs baseline: 4.6839x; 1.0033x over previous
#include <cuda_runtime.h>
#include <cuda_bf16.h>
#include <cstdint>
#include <math.h>

// Problem shape (fixed by setup_inputs)
#define Bn 2048
#define Kn 256
#define Dn 512

// bf16 staging buffers (__device__ globals: allocation-free)
__device__ __nv_bfloat16 g_abig[Bn * 1024];  // [b][ 0..511: x^2 | 512..1023: x ]
__device__ __nv_bfloat16 g_bmat[Kn * 1024];  // [k][ 0..511: bw  | 512..1023: -2*bw*c ]
__device__ __nv_bfloat16 g_rbf [Bn * Kn];    // rbf result, K-major for GEMM2
__device__ __nv_bfloat16 g_wt  [Dn * Kn];    // softplus(W) transposed: [d][k]
__device__ float         g_ck  [Kn];         // sum_d bw*c^2

// ---------------------------------------------------------------------------
// Helpers (arch-generic: ldmatrix / mma.sync / cp.async — NO tcgen05, the
// harness PTX stage targets plain compute_103)
// ---------------------------------------------------------------------------
__device__ __forceinline__ uint32_t s2u(const void* p) {
    uint32_t a;
    asm("{ .reg .u64 t; cvta.to.shared.u64 t, %1; cvt.u32.u64 %0, t; }"
        : "=r"(a) : "l"(p));
    return a;
}
#define SW128(o) ((o) ^ (((o) >> 3) & 0x70))

__device__ __forceinline__ void cp16(uint32_t s, const void* g) {
    asm volatile("cp.async.cg.shared.global [%0], [%1], 16;" :: "r"(s), "l"(g));
}

__device__ __forceinline__ void ldsm4(uint32_t* r, uint32_t addr) {
    asm volatile("ldmatrix.sync.aligned.m8n8.x4.shared.b16 {%0,%1,%2,%3}, [%4];"
                 : "=r"(r[0]), "=r"(r[1]), "=r"(r[2]), "=r"(r[3]) : "r"(addr));
}

__device__ __forceinline__ void mma16816(float* c, const uint32_t* a, const uint32_t* b) {
    asm volatile(
        "mma.sync.aligned.m16n8k16.row.col.f32.bf16.bf16.f32 "
        "{%0,%1,%2,%3}, {%4,%5,%6,%7}, {%8,%9}, {%0,%1,%2,%3};"
        : "+f"(c[0]), "+f"(c[1]), "+f"(c[2]), "+f"(c[3])
        : "r"(a[0]), "r"(a[1]), "r"(a[2]), "r"(a[3]), "r"(b[0]), "r"(b[1]));
}

// ---------------------------------------------------------------------------
// Fused prep: one launch, 512 blocks x 256 threads.
//   blocks [0,256):   A-matrix build, MLP=4 (4 float4 loads in flight)
//   blocks [256,384): B-matrix build + ck reduction
//   blocks [384,512): W softplus + transpose
// ---------------------------------------------------------------------------
__global__ void __launch_bounds__(256)
prep_all(const float* __restrict__ x, const float* __restrict__ centers,
         const float* __restrict__ bandwidths, const float* __restrict__ raw) {
    const int bid = blockIdx.x, tid = threadIdx.x;

    if (bid < 256) {                         // ---- prepA (MLP=4) ----
        const int base = bid * 256 + tid;    // float4 index, stride 65536
        float4 v[4];
        #pragma unroll
        for (int j = 0; j < 4; j++)
            v[j] = ((const float4*)x)[base + j * 65536];
        #pragma unroll
        for (int j = 0; j < 4; j++) {
            const int e4 = (base + j * 65536) * 4;
            const int row = e4 >> 9;
            const int d = e4 & 511;
            __nv_bfloat162* ps = (__nv_bfloat162*)&g_abig[row * 1024 + d];
            ps[0] = __floats2bfloat162_rn(v[j].x * v[j].x, v[j].y * v[j].y);
            ps[1] = __floats2bfloat162_rn(v[j].z * v[j].z, v[j].w * v[j].w);
            __nv_bfloat162* px = (__nv_bfloat162*)&g_abig[row * 1024 + 512 + d];
            px[0] = __floats2bfloat162_rn(v[j].x, v[j].y);
            px[1] = __floats2bfloat162_rn(v[j].z, v[j].w);
        }
        return;
    }

    if (bid < 384) {                         // ---- prepB + ck ----
        const int kb = (bid - 256) * 2;      // 2 k-rows per block
        const int kloc = tid >> 7;           // 0/1
        const int j = tid & 127;             // float4 within row
        const int k = kb + kloc;
        const int base = k * 512 + j * 4;    // element index
        float4 b = *(const float4*)&bandwidths[base];
        float4 cc = *(const float4*)&centers[base];
        const int d = j * 4;
        __nv_bfloat162* pb = (__nv_bfloat162*)&g_bmat[k * 1024 + d];
        pb[0] = __floats2bfloat162_rn(b.x, b.y);
        pb[1] = __floats2bfloat162_rn(b.z, b.w);
        __nv_bfloat162* pc = (__nv_bfloat162*)&g_bmat[k * 1024 + 512 + d];
        pc[0] = __floats2bfloat162_rn(-2.0f * b.x * cc.x, -2.0f * b.y * cc.y);
        pc[1] = __floats2bfloat162_rn(-2.0f * b.z * cc.z, -2.0f * b.w * cc.w);
        float s = b.x * cc.x * cc.x + b.y * cc.y * cc.y
                + b.z * cc.z * cc.z + b.w * cc.w * cc.w;
        #pragma unroll
        for (int o = 16; o > 0; o >>= 1)
            s += __shfl_down_sync(0xffffffffu, s, o);
        __shared__ float red[8];
        if ((tid & 31) == 0) red[tid >> 5] = s;
        __syncthreads();
        if ((tid & 127) == 0) {
            const int rb = kloc * 4;
            g_ck[k] = (red[rb] + red[rb + 1]) + (red[rb + 2] + red[rb + 3]);
        }
        return;
    }

    {                                        // ---- prepW ----
        const int t2 = bid - 384;
        const int d0 = (t2 & 15) * 32, k0 = (t2 >> 4) * 32;
        const int tx = tid & 31, ty = tid >> 5;          // 32 x 8
        __shared__ float t[32][33];
        if (ty < 8) {
            #pragma unroll
            for (int jj = 0; jj < 4; jj++) {
                int k = k0 + ty + jj * 8;
                float r = raw[k * Dn + d0 + tx];
                t[ty + jj * 8][tx] = fmaxf(r, 0.0f) + __logf(1.0f + __expf(-fabsf(r)));
            }
        }
        __syncthreads();
        if (ty < 8) {
            #pragma unroll
            for (int jj = 0; jj < 4; jj++) {
                int d = d0 + ty + jj * 8;
                g_wt[d * Kn + k0 + tx] = __float2bfloat16(t[tx][ty + jj * 8]);
            }
        }
    }
}

// ---------------------------------------------------------------------------
// HMMA bf16 GEMM, split-K across two warp groups:
//   C[64,64] fp32 = A[64,Kd] x B[64,Kd]^T  (both K-major)
// 256 threads / 8 warps. Group 0 (warps 0-3) computes even K-chunks, group 1
// odd chunks; partials reduced through smem at the end. 6-stage cp.async
// pipeline (96 KB smem), chunks loaded in pairs, one barrier per pair.
//   ISG2=false: A=g_abig, B=g_bmat (LD 1024), 16 chunks; exp -> bf16 g_rbf
//   ISG2=true:  A=g_rbf,  B=g_wt   (LD 256),   4 chunks; 1/(h+eps) -> out
// ---------------------------------------------------------------------------
#define STAGE_BYTES 16384     // per chunk: A 8K + B 8K
#define NSTAGE 6
#define SMEMSZ (NSTAGE * STAGE_BYTES)   // 98304

template<bool ISG2>
__global__ void __launch_bounds__(256)
gemm_kern(float* __restrict__ out) {
    constexpr int LD     = ISG2 ? 256 : 1024;
    constexpr int NCHUNK = ISG2 ? 4   : 16;
    constexpr int NSTEP  = NCHUNK / 2;
    const __nv_bfloat16* __restrict__ A  = ISG2 ? g_rbf : g_abig;
    const __nv_bfloat16* __restrict__ Bm = ISG2 ? g_wt  : g_bmat;

    extern __shared__ char sm[];
    const uint32_t T0 = s2u(sm);
    const int tid = threadIdx.x, wid = tid >> 5, l = tid & 31;
    const int m0 = blockIdx.x * 64, n0 = blockIdx.y * 64;
    const int grp = wid >> 2, wg = wid & 3;
    const int wm = wg & 1, wn = wg >> 1;

    // ldmatrix lane-derived constants
    const int lr  = l & 7, sel = l >> 3;
    const int a_row = wm * 32 + (sel & 1) * 8 + lr;        // + mi*16
    const uint32_t a_kb = (uint32_t)((sel >> 1) * 16);     // + ks*32
    const int b_row = wn * 32 + (sel >> 1) * 8 + lr;       // + bi*16
    const uint32_t b_kb = (uint32_t)((sel & 1) * 16);

    // load chunk ch into stage ch%NSTAGE (256 threads: 2 A + 2 B cp16 each)
    #define LOAD_CHUNK(ch) do {                                              \
        uint32_t _sa = T0 + ((ch) % NSTAGE) * STAGE_BYTES;                   \
        const __nv_bfloat16* _ga = A  + (size_t)m0 * LD + (ch) * 64;         \
        const __nv_bfloat16* _gb = Bm + (size_t)n0 * LD + (ch) * 64;         \
        _Pragma("unroll")                                                    \
        for (int q = 0; q < 2; q++) {                                        \
            int u = tid + q * 256;                                           \
            int r = u >> 3, cc = u & 7;                                      \
            uint32_t off = SW128((uint32_t)(r * 128 + cc * 16));             \
            cp16(_sa        + off, _ga + (size_t)r * LD + cc * 8);           \
            cp16(_sa + 8192 + off, _gb + (size_t)r * LD + cc * 8);           \
        }                                                                    \
    } while (0)

    #define LOAD_PAIR(p) do {                                                \
        LOAD_CHUNK(2 * (p));                                                 \
        LOAD_CHUNK(2 * (p) + 1);                                             \
        asm volatile("cp.async.commit_group;");                              \
    } while (0)

    float acc[2][4][4];
    #pragma unroll
    for (int mi = 0; mi < 2; mi++)
        #pragma unroll
        for (int nj = 0; nj < 4; nj++)
            #pragma unroll
            for (int e = 0; e < 4; e++) acc[mi][nj][e] = 0.0f;

    LOAD_PAIR(0);
    if (NSTEP > 1) LOAD_PAIR(1);

    for (int t = 0; t < NSTEP; t++) {
        if (t < NSTEP - 1) asm volatile("cp.async.wait_group 1;");
        else               asm volatile("cp.async.wait_group 0;");
        // Barrier: pair t resident for all; pair t-1 compute done by all, so
        // pair t+2's stages ((2t+4)%6 == pair t-1's) are free to overwrite.
        __syncthreads();
        if (t + 2 < NSTEP) LOAD_PAIR(t + 2);

        const int ch = 2 * t + grp;          // this group's chunk
        const uint32_t sa  = T0 + (ch % NSTAGE) * STAGE_BYTES;
        const uint32_t sbb = sa + 8192;
        #pragma unroll
        for (int ks = 0; ks < 4; ks++) {
            uint32_t a[2][4], b[2][4];
            #pragma unroll
            for (int mi = 0; mi < 2; mi++)
                ldsm4(a[mi], sa + SW128((uint32_t)((a_row + mi * 16) * 128)
                                        + (uint32_t)(ks * 32) + a_kb));
            #pragma unroll
            for (int bi = 0; bi < 2; bi++)
                ldsm4(b[bi], sbb + SW128((uint32_t)((b_row + bi * 16) * 128)
                                         + (uint32_t)(ks * 32) + b_kb));
            #pragma unroll
            for (int mi = 0; mi < 2; mi++)
                #pragma unroll
                for (int nj = 0; nj < 4; nj++)
                    mma16816(acc[mi][nj], a[mi], &b[nj >> 1][(nj & 1) * 2]);
        }
    }
    #undef LOAD_PAIR
    #undef LOAD_CHUNK

    // ---- cross-group reduce through smem (pitch 72 floats) ---------------
    float* Rb = (float*)sm;
    const int rrow = wm * 32 + (l >> 2);
    const int rcol = wn * 32 + 2 * (l & 3);
    __syncthreads();                          // all compute done, stages dead
    if (grp == 1) {
        #pragma unroll
        for (int mi = 0; mi < 2; mi++)
            #pragma unroll
            for (int nj = 0; nj < 4; nj++) {
                const int r = rrow + mi * 16, c = rcol + nj * 8;
                *(float2*)&Rb[r * 72 + c]       = make_float2(acc[mi][nj][0], acc[mi][nj][1]);
                *(float2*)&Rb[(r + 8) * 72 + c] = make_float2(acc[mi][nj][2], acc[mi][nj][3]);
            }
    }
    __syncthreads();
    if (grp == 1) return;

    #pragma unroll
    for (int mi = 0; mi < 2; mi++)
        #pragma unroll
        for (int nj = 0; nj < 4; nj++) {
            const int r = rrow + mi * 16, c = rcol + nj * 8;
            float2 p0 = *(const float2*)&Rb[r * 72 + c];
            float2 p1 = *(const float2*)&Rb[(r + 8) * 72 + c];
            acc[mi][nj][0] += p0.x;  acc[mi][nj][1] += p0.y;
            acc[mi][nj][2] += p1.x;  acc[mi][nj][3] += p1.y;
        }

    // ---- Epilogue (group 0 only) -----------------------------------------
    const int erow = m0 + rrow;

    if (!ISG2) {
        float ckc[8];
        #pragma unroll
        for (int nj = 0; nj < 4; nj++) {
            ckc[2 * nj]     = g_ck[n0 + rcol + nj * 8];
            ckc[2 * nj + 1] = g_ck[n0 + rcol + nj * 8 + 1];
        }
        #pragma unroll
        for (int mi = 0; mi < 2; mi++) {
            #pragma unroll
            for (int nj = 0; nj < 4; nj++) {
                const int col = rcol + nj * 8;
                const int r = erow + mi * 16;
                float v0 = __expf(-0.5f * (acc[mi][nj][0] + ckc[2 * nj]));
                float v1 = __expf(-0.5f * (acc[mi][nj][1] + ckc[2 * nj + 1]));
                float v2 = __expf(-0.5f * (acc[mi][nj][2] + ckc[2 * nj]));
                float v3 = __expf(-0.5f * (acc[mi][nj][3] + ckc[2 * nj + 1]));
                __nv_bfloat162 p0 = __floats2bfloat162_rn(v0, v1);
                __nv_bfloat162 p1 = __floats2bfloat162_rn(v2, v3);
                *(__nv_bfloat162*)&g_rbf[(size_t)r * Kn + n0 + col]       = p0;
                *(__nv_bfloat162*)&g_rbf[(size_t)(r + 8) * Kn + n0 + col] = p1;
            }
        }
    } else {
        const float eps = 1e-3f;
        #pragma unroll
        for (int mi = 0; mi < 2; mi++) {
            #pragma unroll
            for (int nj = 0; nj < 4; nj++) {
                const int col = n0 + rcol + nj * 8;
                const int r = erow + mi * 16;
                float2 o0, o1;
                o0.x = __fdividef(1.0f, acc[mi][nj][0] + eps);
                o0.y = __fdividef(1.0f, acc[mi][nj][1] + eps);
                o1.x = __fdividef(1.0f, acc[mi][nj][2] + eps);
                o1.y = __fdividef(1.0f, acc[mi][nj][3] + eps);
                *(float2*)(out + (size_t)r * Dn + col)       = o0;
                *(float2*)(out + (size_t)(r + 8) * Dn + col) = o1;
            }
        }
    }
}

// ---------------------------------------------------------------------------
extern "C" void kernel_launch(void* const* d_in, const int* in_sizes, int n_in,
                              void* d_out, int out_size) {
    const float* x           = (const float*)d_in[0];
    const float* centers     = (const float*)d_in[1];
    const float* bandwidths  = (const float*)d_in[2];
    const float* raw_weights = (const float*)d_in[3];
    float* out = (float*)d_out;

    static bool attr_set = false;
    if (!attr_set) {
        cudaFuncSetAttribute(gemm_kern<false>,
                             cudaFuncAttributeMaxDynamicSharedMemorySize, SMEMSZ);
        cudaFuncSetAttribute(gemm_kern<true>,
                             cudaFuncAttributeMaxDynamicSharedMemorySize, SMEMSZ);
        attr_set = true;
    }

    prep_all<<<512, 256>>>(x, centers, bandwidths, raw_weights);

    // G1: dist GEMM (M=2048, N=256, K=1024) -> rbf (bf16)
    gemm_kern<false><<<dim3(Bn / 64, Kn / 64), 256, SMEMSZ>>>(nullptr);
    // G2: h GEMM (M=2048, N=512, K=256) -> out = 1/(h+eps)
    gemm_kern<true><<<dim3(Bn / 64, Dn / 64), 256, SMEMSZ>>>(out);
}